// round 17
// baseline (speedup 1.0000x reference)
#include <cuda_runtime.h>

// CRF Viterbi decode: B=1024, T=512, C=48
// R15: 64-thread quad layout. Thread t: quad u=t>>2 owns classes {3u,3u+1,3u+2},
// quarter m=t&3 owns source range [12m,12m+12). Zero wasted lanes: 2304 slots/64.
// Per-class: 12-way local tree + 2 shfl_xor rounds in the quad (first-max exact).
// 1024 blocks x 64 threads, 25KB smem -> all co-resident (6.9 blocks/SM).

#define BB 1024
#define TT 512
#define CC 48

// local argmax over 12 sums (first-max; strict '>' only prefers higher index)
__device__ __forceinline__ void reduce12(const float* __restrict__ s,
                                         const float* __restrict__ c,
                                         float& mv, int& ma)
{
    float v[12];
#pragma unroll
    for (int k = 0; k < 12; ++k) v[k] = s[k] + c[k];

    float w[6]; int a[6];
#pragma unroll
    for (int q = 0; q < 6; ++q) {
        bool p = v[2 * q + 1] > v[2 * q];
        w[q] = p ? v[2 * q + 1] : v[2 * q];
        a[q] = p ? (2 * q + 1) : (2 * q);
    }
#pragma unroll
    for (int q = 0; q < 3; ++q) {
        bool p = w[2 * q + 1] > w[2 * q];
        w[q] = p ? w[2 * q + 1] : w[2 * q];
        a[q] = p ? a[2 * q + 1] : a[2 * q];
    }
    bool  p1 = w[1] > w[0];
    float m  = p1 ? w[1] : w[0];
    int   x  = p1 ? a[1] : a[0];
    bool  p2 = w[2] > m;
    mv = p2 ? w[2] : m;
    ma = p2 ? a[2] : x;
}

// quad combine round: partner = lane^d; 'ishi' = my quarter has higher indices
__device__ __forceinline__ void qcombine(float& v, int& a, int d, bool ishi)
{
    float ov = __shfl_xor_sync(0xFFFFFFFFu, v, d);
    int   oa = __shfl_xor_sync(0xFFFFFFFFu, a, d);
    float lov = ishi ? ov : v;  int loa = ishi ? oa : a;
    float hiv = ishi ? v : ov;  int hia = ishi ? a : oa;
    bool  p = hiv > lov;
    v = p ? hiv : lov;
    a = p ? hia : loa;
}

__global__ __launch_bounds__(64, 8)
void viterbi_kernel(const float* __restrict__ pot,
                    const int*   __restrict__ seq_len,
                    const float* __restrict__ trans,
                    float*       __restrict__ out)
{
    __shared__ float         s_score[2][CC];
    __shared__ unsigned char s_bp[(TT - 1) * CC];
    __shared__ unsigned char s_tags[TT];
    __shared__ int           s_lasttag;

    const int b   = blockIdx.x;
    const int tid = threadIdx.x;        // [0,64)
    const int u   = tid >> 2;           // class triple [0,16)
    const int m   = tid & 3;            // source quarter
    const int j0  = 3 * u, j1 = 3 * u + 1, j2 = 3 * u + 2;
    const int ib  = 12 * m;             // source base

    // transition slices: c?[k] = trans[ib+k][j?]
    float c0[12], c1[12], c2[12];
#pragma unroll
    for (int k = 0; k < 12; ++k) {
        c0[k] = trans[(ib + k) * CC + j0];
        c1[k] = trans[(ib + k) * CC + j1];
        c2[k] = trans[(ib + k) * CC + j2];
    }

    const float* potb = pot + (size_t)b * TT * CC;
    int L = seq_len[b];
    if (L > TT) L = TT;
    if (L < 1)  L = 1;

    if (tid < CC) s_score[0][tid] = potb[tid];

    // depth-2 potential prefetch for the 3 owned classes (clamped, in-bounds)
    float pn0 = potb[CC + j0];
    float pn1 = potb[CC + j1];
    float pn2 = potb[CC + j2];
    __syncthreads();

    int buf = 0;
    for (int t = 1; t < L; ++t) {
        float pa = pn0, pb = pn1, pc = pn2;
        int tn = t + 1; if (tn > TT - 1) tn = TT - 1;
        pn0 = potb[tn * CC + j0];
        pn1 = potb[tn * CC + j1];
        pn2 = potb[tn * CC + j2];

        // my quarter's 12 scores (3x LDS.128; 16-lane broadcast groups)
        float sc[12];
        {
            const float4* s4 = reinterpret_cast<const float4*>(&s_score[buf][ib]);
#pragma unroll
            for (int q = 0; q < 3; ++q) {
                float4 v4 = s4[q];
                sc[4 * q + 0] = v4.x; sc[4 * q + 1] = v4.y;
                sc[4 * q + 2] = v4.z; sc[4 * q + 3] = v4.w;
            }
        }

        // three independent local reductions (ILP streams)
        float v0, v1, v2; int a0, a1, a2;
        reduce12(sc, c0, v0, a0);
        reduce12(sc, c1, v1, a1);
        reduce12(sc, c2, v2, a2);
        a0 += ib; a1 += ib; a2 += ib;

        // quad combines: round xor1 (hi if m&1), round xor2 (hi if m&2)
        const bool h1 = (m & 1), h2 = (m & 2);
        qcombine(v0, a0, 1, h1); qcombine(v1, a1, 1, h1); qcombine(v2, a2, 1, h1);
        qcombine(v0, a0, 2, h2); qcombine(v1, a1, 2, h2); qcombine(v2, a2, 2, h2);

        // quarter 0 stores results for its 3 classes
        if (m == 0) {
            float* nxt = s_score[buf ^ 1];
            nxt[j0] = v0 + pa;
            nxt[j1] = v1 + pb;
            nxt[j2] = v2 + pc;
            unsigned char* bpr = s_bp + (t - 1) * CC;
            bpr[j0] = (unsigned char)a0;
            bpr[j1] = (unsigned char)a1;
            bpr[j2] = (unsigned char)a2;
        }
        buf ^= 1;
        __syncthreads();
    }

    // final argmax (first-max wins)
    if (tid == 0) {
        const float* fin = s_score[buf];
        float bestv = fin[0]; int tag = 0;
#pragma unroll
        for (int i = 1; i < CC; ++i) {
            float v = fin[i];
            if (v > bestv) { bestv = v; tag = i; }
        }
        s_lasttag = tag;
    }
    __syncthreads();

    const int tag0 = s_lasttag;
    // identity tail fill: t in [L-1, TT-1]
    for (int t = L - 1 + tid; t < TT; t += 64) s_tags[t] = (unsigned char)tag0;

    // serial backtrack (smem pointer chase)
    if (tid == 0) {
        int tag = tag0;
        for (int t = L - 1; t >= 1; --t) {
            tag = s_bp[(t - 1) * CC + tag];
            s_tags[t - 1] = (unsigned char)tag;
        }
    }
    __syncthreads();

    // one-hot output: 6144 float4/row, coalesced
    float4* ob = reinterpret_cast<float4*>(out + (size_t)b * TT * CC);
    const int NQ = TT * (CC / 4);
    for (int q = tid; q < NQ; q += 64) {
        int t  = q / (CC / 4);
        int r  = q % (CC / 4);
        int tg = s_tags[t];
        int e  = r * 4;
        float4 v;
        v.x = (e + 0 == tg) ? 1.0f : 0.0f;
        v.y = (e + 1 == tg) ? 1.0f : 0.0f;
        v.z = (e + 2 == tg) ? 1.0f : 0.0f;
        v.w = (e + 3 == tg) ? 1.0f : 0.0f;
        ob[q] = v;
    }
}

extern "C" void kernel_launch(void* const* d_in, const int* in_sizes, int n_in,
                              void* d_out, int out_size)
{
    const float* pot    = (const float*)d_in[0];
    const int*   seqlen = (const int*)d_in[1];
    const float* trans  = (const float*)d_in[2];
    float*       out    = (float*)d_out;

    viterbi_kernel<<<BB, 64>>>(pot, seqlen, trans, out);
}